// round 9
// baseline (speedup 1.0000x reference)
#include <cuda_runtime.h>
#include <cstdint>

// ---------------------------------------------------------------------------
// Problem constants
// ---------------------------------------------------------------------------
#define BB 32
#define LL 256
#define SS 128
#define AA 16
#define RR 4
#define M_TOK 8192        // B*L
#define K0 132            // S + R
#define K0P 136           // padded to /8
#define D1 2112
#define D2 4224
#define D3 8448
#define D4 4224
#define D5 64

// GEMM geometry: CTA 128x128, BK=16, 8 warps (4x2) of 32x64.
// A raw f32 (split at read), B pre-split hi/lo in global, 4-stage cp.async.
#define BK 16
#define A_STRIDE 20                      // floats per A row (16 + 4 pad)
#define B_STRIDE 136                     // floats per B k-row (128 + 8 pad)
#define A_BYTES (128 * A_STRIDE * 4)     // 10240
#define B_BYTES (BK * B_STRIDE * 4)      // 8704
#define STAGE_BYTES (A_BYTES + 2 * B_BYTES)  // 27648
#define NSTAGE 4
#define SMB (NSTAGE * STAGE_BYTES)       // 110592

// Weight pre-split offsets (elements)
#define WO1 0
#define WO2 278784                       // + 132*2112
#define WO3 9199872                      // + 2112*4224
#define WO4 44884224                     // + 4224*8448
#define WO5 80568576                     // + 8448*4224
#define WTOT 80838912                    // + 4224*64

// ---------------------------------------------------------------------------
// Scratch (static device globals; no allocation at runtime)
// ---------------------------------------------------------------------------
__device__ float g_x0[M_TOK * K0P];
__device__ float g_a1[M_TOK * D1];
__device__ float g_a2[M_TOK * D2];
__device__ float g_a3[M_TOK * D3];
__device__ float g_a4[M_TOK * D4];
__device__ float g_wh[WTOT];
__device__ float g_wl[WTOT];

// ---------------------------------------------------------------------------
// Helpers
// ---------------------------------------------------------------------------
__device__ __forceinline__ uint32_t smem_u32(const void* p) {
    uint32_t a;
    asm("{ .reg .u64 t; cvta.to.shared.u64 t, %1; cvt.u32.u64 %0, t; }" : "=r"(a) : "l"(p));
    return a;
}

__device__ __forceinline__ void cp16(uint32_t dst, const void* src, int pred16) {
    asm volatile("cp.async.cg.shared.global [%0], [%1], 16, %2;"
                 :: "r"(dst), "l"(src), "r"(pred16) : "memory");
}
#define CP_COMMIT() asm volatile("cp.async.commit_group;" ::: "memory")
#define CP_WAIT2()  asm volatile("cp.async.wait_group 2;" ::: "memory")

// split fp32 -> exact tf32 hi (mask-truncate) + fp32 residual lo
__device__ __forceinline__ void split(float x, float& hi, float& lo) {
    hi = __uint_as_float(__float_as_uint(x) & 0xFFFFE000u);
    lo = x - hi;
}

__device__ __forceinline__ void mma8(float* c, const float* a, const float* b) {
    asm volatile(
        "mma.sync.aligned.m16n8k8.row.col.f32.tf32.tf32.f32 "
        "{%0,%1,%2,%3},{%4,%5,%6,%7},{%8,%9},{%0,%1,%2,%3};\n"
        : "+f"(c[0]), "+f"(c[1]), "+f"(c[2]), "+f"(c[3])
        : "r"(__float_as_uint(a[0])), "r"(__float_as_uint(a[1])),
          "r"(__float_as_uint(a[2])), "r"(__float_as_uint(a[3])),
          "r"(__float_as_uint(b[0])), "r"(__float_as_uint(b[1])));
}

// ---------------------------------------------------------------------------
// Weight pre-split: W -> (hi, lo), element-wise float4
// ---------------------------------------------------------------------------
__global__ void k_wsplit(const float* __restrict__ W, float* __restrict__ Wh,
                         float* __restrict__ Wl, int n4) {
    int i = blockIdx.x * blockDim.x + threadIdx.x;
    if (i >= n4) return;
    float4 v = ((const float4*)W)[i];
    float4 h, l;
    split(v.x, h.x, l.x); split(v.y, h.y, l.y);
    split(v.z, h.z, l.z); split(v.w, h.w, l.w);
    ((float4*)Wh)[i] = h;
    ((float4*)Wl)[i] = l;
}

// ---------------------------------------------------------------------------
// Concat: X0[row, 0:128] = state, [128:132] = preference, [132:136] = 0
// ---------------------------------------------------------------------------
__global__ void k_concat(const float* __restrict__ st, const float* __restrict__ pf,
                         float* __restrict__ x0) {
    int idx = blockIdx.x * blockDim.x + threadIdx.x;
    if (idx >= M_TOK * K0P) return;
    int row = idx / K0P;
    int c   = idx - row * K0P;
    float v;
    if (c < SS)        v = st[row * SS + c];
    else if (c < K0)   v = pf[row * RR + (c - SS)];
    else               v = 0.0f;
    x0[idx] = v;
}

// ---------------------------------------------------------------------------
// GEMM: C[M,N] = act(A[M,KA] @ W[KW,N] + bias)   (3xTF32, mma.sync)
// Wh/Wl: pre-split tf32-hi / residual-lo weights, same [KW][N] layout.
// ---------------------------------------------------------------------------
template <bool RELU>
__global__ __launch_bounds__(256, 2)
void k_gemm(const float* __restrict__ A, const float* __restrict__ Wh,
            const float* __restrict__ Wl, const float* __restrict__ bias,
            float* __restrict__ C, int N, int KA, int KW)
{
    extern __shared__ char smem[];
    const uint32_t sb = smem_u32(smem);

    const int tid  = threadIdx.x;
    const int bm   = blockIdx.y * 128;
    const int n0   = blockIdx.x * 128;
    const int lane = tid & 31;
    const int wid  = tid >> 5;
    const int wm   = wid & 3;          // 0..3 -> 32 rows each
    const int wn   = wid >> 2;         // 0..1 -> 64 cols each
    const int grp  = lane >> 2;
    const int tig  = lane & 3;

    // ---- cp.async load mappings ----
    // A: 128 rows x 16k; thread -> row tid>>1, two 16B chunks at (tid&1)*2
    const int a_row = tid >> 1;
    const int a_c0  = (tid & 1) * 2;
    // B: 16 krows x 128n; thread -> krow tid>>4, chunks (tid&15), +16 (linear)
    const int b_kr  = tid >> 4;
    const int b_nf  = (tid & 15) * 4;

    const long a_rowbase = (long)(bm + a_row) * KA;
    const int  n_ok0 = (n0 + b_nf)      < N ? 16 : 0;
    const int  n_ok1 = (n0 + b_nf + 64) < N ? 16 : 0;

    const int T = (KA + BK - 1) >> 4;

    auto load_stage = [&](int t, int slot) {
        uint32_t st = sb + slot * STAGE_BYTES;
        // A (raw f32)
        {
            int kg0 = t * BK + a_c0 * 4;
            uint32_t d = st + (a_row * A_STRIDE + a_c0 * 4) * 4;
#pragma unroll
            for (int u = 0; u < 2; u++) {
                int kg = kg0 + u * 4;
                int sz = (kg < KA) ? 16 : 0;
                int kc = (kg < KA) ? kg : 0;
                cp16(d + u * 16, A + a_rowbase + kc, sz);
            }
        }
        // B hi + lo (pre-split)
        {
            int kr  = t * BK + b_kr;
            int kok = kr < KW;
            long rb = (long)(kok ? kr : 0) * N + n0;
            uint32_t dh = st + A_BYTES + (b_kr * B_STRIDE + b_nf) * 4;
            uint32_t dl = dh + B_BYTES;
            cp16(dh,       Wh + rb + b_nf,      kok ? n_ok0 : 0);
            cp16(dh + 256, Wh + rb + b_nf + 64, kok ? n_ok1 : 0);
            cp16(dl,       Wl + rb + b_nf,      kok ? n_ok0 : 0);
            cp16(dl + 256, Wl + rb + b_nf + 64, kok ? n_ok1 : 0);
        }
    };

    float c[2][8][4];
#pragma unroll
    for (int mt = 0; mt < 2; mt++)
#pragma unroll
        for (int nt = 0; nt < 8; nt++)
#pragma unroll
            for (int j = 0; j < 4; j++) c[mt][nt][j] = 0.0f;

    // prologue: stages 0..2
#pragma unroll
    for (int s = 0; s < NSTAGE - 1; s++) {
        if (s < T) load_stage(s, s);
        CP_COMMIT();
    }

    for (int t = 0; t < T; t++) {
        CP_WAIT2();
        __syncthreads();
        {
            int lt = t + NSTAGE - 1;
            if (lt < T) load_stage(lt, lt & (NSTAGE - 1));
            CP_COMMIT();
        }
        const int slot = t & (NSTAGE - 1);
        const float* As = (const float*)(smem + slot * STAGE_BYTES);
        const float* Bh = (const float*)(smem + slot * STAGE_BYTES + A_BYTES);
        const float* Bl = (const float*)(smem + slot * STAGE_BYTES + A_BYTES + B_BYTES);

#pragma unroll
        for (int kk = 0; kk < BK; kk += 8) {
            float ah[2][4], al[2][4];
#pragma unroll
            for (int mt = 0; mt < 2; mt++) {
                int rb = (wm * 32 + mt * 16 + grp) * A_STRIDE + kk + tig;
                split(As[rb],                    ah[mt][0], al[mt][0]);
                split(As[rb + 8 * A_STRIDE],     ah[mt][1], al[mt][1]);
                split(As[rb + 4],                ah[mt][2], al[mt][2]);
                split(As[rb + 8 * A_STRIDE + 4], ah[mt][3], al[mt][3]);
            }
#pragma unroll
            for (int nt = 0; nt < 8; nt++) {
                int cb = wn * 64 + nt * 8 + grp;
                float bh[2], bl[2];
                bh[0] = Bh[(kk + tig) * B_STRIDE + cb];
                bh[1] = Bh[(kk + tig + 4) * B_STRIDE + cb];
                bl[0] = Bl[(kk + tig) * B_STRIDE + cb];
                bl[1] = Bl[(kk + tig + 4) * B_STRIDE + cb];
#pragma unroll
                for (int mt = 0; mt < 2; mt++) {
                    mma8(c[mt][nt], ah[mt], bh);   // hi*hi
                    mma8(c[mt][nt], al[mt], bh);   // lo*hi
                    mma8(c[mt][nt], ah[mt], bl);   // hi*lo
                }
            }
        }
    }

    // epilogue: bias (+ relu), guarded stores
#pragma unroll
    for (int mt = 0; mt < 2; mt++) {
        int r = bm + wm * 32 + mt * 16 + grp;
#pragma unroll
        for (int nt = 0; nt < 8; nt++) {
            int col = n0 + wn * 64 + nt * 8 + tig * 2;
            if (col < N) {
                float bv0 = bias[col], bv1 = bias[col + 1];
                float v0 = c[mt][nt][0] + bv0;
                float v1 = c[mt][nt][1] + bv1;
                float v2 = c[mt][nt][2] + bv0;
                float v3 = c[mt][nt][3] + bv1;
                if (RELU) {
                    v0 = fmaxf(v0, 0.f); v1 = fmaxf(v1, 0.f);
                    v2 = fmaxf(v2, 0.f); v3 = fmaxf(v3, 0.f);
                }
                C[(long)r * N + col]           = v0;
                C[(long)r * N + col + 1]       = v1;
                C[(long)(r + 8) * N + col]     = v2;
                C[(long)(r + 8) * N + col + 1] = v3;
            }
        }
    }
}

// ---------------------------------------------------------------------------
// _H epilogue (exact replication of reference index gymnastics).
// ---------------------------------------------------------------------------
__global__ void k_h(const float* __restrict__ q, const float* __restrict__ w,
                    float* __restrict__ hq) {
    const int i  = blockIdx.x;   // 0..31
    const int l2 = threadIdx.x;  // 0..255
    __shared__ int   s_ind[LL];
    __shared__ float s_sel[LL * 4];

    const int rsel = l2 >> 6;
    const int lb   = (l2 & 63) * 4;

    const float w0 = w[(i * LL + l2) * RR + 0];
    const float w1 = w[(i * LL + l2) * RR + 1];
    const float w2 = w[(i * LL + l2) * RR + 2];
    const float w3 = w[(i * LL + l2) * RR + 3];

    float best = -3.402823466e38f;
    int bk = 0;
    const int nb = (64 * i) & 511;
    for (int k = 0; k < 64; ++k) {
        int n  = (nb + k) & 511;
        int bp = n >> 4, a = n & 15;
        int sbp = (bp >> 2) + ((bp & 3) << 3);
        const float* qp = q + ((long)(sbp * LL + lb) * AA + a) * RR + rsel;
        float u = qp[0] * w0 + qp[64] * w1 + qp[128] * w2 + qp[192] * w3;
        if (u > best) { best = u; bk = k; }
    }
    s_ind[l2] = bk;
    {
        int n  = (nb + bk) & 511;
        int bp = n >> 4, a = n & 15;
        int sbp = (bp >> 2) + ((bp & 3) << 3);
        const float* qp = q + ((long)(sbp * LL + lb) * AA + a) * RR + rsel;
        s_sel[l2 * 4 + 0] = qp[0];
        s_sel[l2 * 4 + 1] = qp[64];
        s_sel[l2 * 4 + 2] = qp[128];
        s_sel[l2 * 4 + 3] = qp[192];
    }
    __syncthreads();

    int key = bk, pos = 0;
    for (int j = 0; j < LL; ++j) {
        int kj = s_ind[j];
        pos += (kj < key) || (kj == key && j < l2);
    }
    float* o = hq + (long)(i * LL + pos) * 4;
    o[0] = s_sel[l2 * 4 + 0];
    o[1] = s_sel[l2 * 4 + 1];
    o[2] = s_sel[l2 * 4 + 2];
    o[3] = s_sel[l2 * 4 + 3];
}

// ---------------------------------------------------------------------------
// Launch
// ---------------------------------------------------------------------------
extern "C" void kernel_launch(void* const* d_in, const int* in_sizes, int n_in,
                              void* d_out, int out_size) {
    const float* state = (const float*)d_in[0];
    const float* pref  = (const float*)d_in[1];
    const float* W1 = (const float*)d_in[3];
    const float* b1 = (const float*)d_in[4];
    const float* W2 = (const float*)d_in[5];
    const float* b2 = (const float*)d_in[6];
    const float* W3 = (const float*)d_in[7];
    const float* b3 = (const float*)d_in[8];
    const float* W4 = (const float*)d_in[9];
    const float* b4 = (const float*)d_in[10];
    const float* W5 = (const float*)d_in[11];
    const float* b5 = (const float*)d_in[12];

    float* out = (float*)d_out;
    float* hq  = out;                        // [8192, 4]
    float* q   = out + BB * LL * RR;         // [32, 256, 16, 4]

    float *x0, *a1, *a2, *a3, *a4, *wh, *wl;
    cudaGetSymbolAddress((void**)&x0, g_x0);
    cudaGetSymbolAddress((void**)&a1, g_a1);
    cudaGetSymbolAddress((void**)&a2, g_a2);
    cudaGetSymbolAddress((void**)&a3, g_a3);
    cudaGetSymbolAddress((void**)&a4, g_a4);
    cudaGetSymbolAddress((void**)&wh, g_wh);
    cudaGetSymbolAddress((void**)&wl, g_wl);

    cudaFuncSetAttribute(k_gemm<true>,  cudaFuncAttributeMaxDynamicSharedMemorySize, SMB);
    cudaFuncSetAttribute(k_gemm<false>, cudaFuncAttributeMaxDynamicSharedMemorySize, SMB);

    // weight pre-split (per launch; ~1% of runtime)
    {
        struct { const float* w; int off; int n; } ws[5] = {
            {W1, WO1, K0 * D1}, {W2, WO2, D1 * D2}, {W3, WO3, D2 * D3},
            {W4, WO4, D3 * D4}, {W5, WO5, D4 * D5}
        };
        for (int i = 0; i < 5; i++) {
            int n4 = ws[i].n / 4;
            k_wsplit<<<(n4 + 255) / 256, 256>>>(ws[i].w, wh + ws[i].off,
                                                wl + ws[i].off, n4);
        }
    }

    k_concat<<<(M_TOK * K0P + 255) / 256, 256>>>(state, pref, x0);

    {
        dim3 g((D1 + 127) / 128, M_TOK / 128);
        k_gemm<true><<<g, 256, SMB>>>(x0, wh + WO1, wl + WO1, b1, a1, D1, K0P, K0);
    }
    {
        dim3 g((D2 + 127) / 128, M_TOK / 128);
        k_gemm<true><<<g, 256, SMB>>>(a1, wh + WO2, wl + WO2, b2, a2, D2, D1, D1);
    }
    {
        dim3 g((D3 + 127) / 128, M_TOK / 128);
        k_gemm<true><<<g, 256, SMB>>>(a2, wh + WO3, wl + WO3, b3, a3, D3, D2, D2);
    }
    {
        dim3 g((D4 + 127) / 128, M_TOK / 128);
        k_gemm<true><<<g, 256, SMB>>>(a3, wh + WO4, wl + WO4, b4, a4, D4, D3, D3);
    }
    {
        dim3 g(1, M_TOK / 128);
        k_gemm<false><<<g, 256, SMB>>>(a4, wh + WO5, wl + WO5, b5, q, D5, D4, D4);
    }

    k_h<<<BB, LL>>>(q, pref, hq);
}

// round 10
// speedup vs baseline: 1.5170x; 1.5170x over previous
#include <cuda_runtime.h>
#include <cstdint>

// ---------------------------------------------------------------------------
// Problem constants
// ---------------------------------------------------------------------------
#define BB 32
#define LL 256
#define SS 128
#define AA 16
#define RR 4
#define M_TOK 8192        // B*L
#define K0 132            // S + R
#define K0P 136           // padded to /8
#define D1 2112
#define D2 4224
#define D3 8448
#define D4 4224
#define D5 64

// GEMM geometry: CTA 128x128, BK=32, 8 warps (4x2) of 32x64, raw-f32 smem,
// split-to-tf32 at read time, 3-stage cp.async pipeline, 2 CTAs/SM.
// B stage-fill uses two 16-row halves with the R7 conflict-free mapping.
#define BK 32
#define A_STRIDE 36                      // floats per A row (32 + 4 pad)
#define B_STRIDE 136                     // floats per B k-row (128 + 8 pad)
#define A_BYTES (128 * A_STRIDE * 4)     // 18432
#define B_BYTES (BK * B_STRIDE * 4)      // 17408
#define STAGE_BYTES (A_BYTES + B_BYTES)  // 35840
#define NSTAGE 3
#define SMB (NSTAGE * STAGE_BYTES)       // 107520

// ---------------------------------------------------------------------------
// Scratch (static device globals; no allocation at runtime)
// ---------------------------------------------------------------------------
__device__ float g_x0[M_TOK * K0P];
__device__ float g_a1[M_TOK * D1];
__device__ float g_a2[M_TOK * D2];
__device__ float g_a3[M_TOK * D3];
__device__ float g_a4[M_TOK * D4];

// ---------------------------------------------------------------------------
// Helpers
// ---------------------------------------------------------------------------
__device__ __forceinline__ uint32_t smem_u32(const void* p) {
    uint32_t a;
    asm("{ .reg .u64 t; cvta.to.shared.u64 t, %1; cvt.u32.u64 %0, t; }" : "=r"(a) : "l"(p));
    return a;
}

__device__ __forceinline__ void cp16(uint32_t dst, const void* src, int pred16) {
    asm volatile("cp.async.cg.shared.global [%0], [%1], 16, %2;"
                 :: "r"(dst), "l"(src), "r"(pred16) : "memory");
}
#define CP_COMMIT() asm volatile("cp.async.commit_group;" ::: "memory")
#define CP_WAIT1()  asm volatile("cp.async.wait_group 1;" ::: "memory")

// split fp32 -> exact tf32 hi (mask-truncate) + fp32 residual lo
__device__ __forceinline__ void split(float x, float& hi, float& lo) {
    hi = __uint_as_float(__float_as_uint(x) & 0xFFFFE000u);
    lo = x - hi;
}

__device__ __forceinline__ void mma8(float* c, const float* a, const float* b) {
    asm volatile(
        "mma.sync.aligned.m16n8k8.row.col.f32.tf32.tf32.f32 "
        "{%0,%1,%2,%3},{%4,%5,%6,%7},{%8,%9},{%0,%1,%2,%3};\n"
        : "+f"(c[0]), "+f"(c[1]), "+f"(c[2]), "+f"(c[3])
        : "r"(__float_as_uint(a[0])), "r"(__float_as_uint(a[1])),
          "r"(__float_as_uint(a[2])), "r"(__float_as_uint(a[3])),
          "r"(__float_as_uint(b[0])), "r"(__float_as_uint(b[1])));
}

// ---------------------------------------------------------------------------
// Concat: X0[row, 0:128] = state, [128:132] = preference, [132:136] = 0
// ---------------------------------------------------------------------------
__global__ void k_concat(const float* __restrict__ st, const float* __restrict__ pf,
                         float* __restrict__ x0) {
    int idx = blockIdx.x * blockDim.x + threadIdx.x;
    if (idx >= M_TOK * K0P) return;
    int row = idx / K0P;
    int c   = idx - row * K0P;
    float v;
    if (c < SS)        v = st[row * SS + c];
    else if (c < K0)   v = pf[row * RR + (c - SS)];
    else               v = 0.0f;
    x0[idx] = v;
}

// ---------------------------------------------------------------------------
// GEMM: C[M,N] = act(A[M,KA] @ W[KW,N] + bias)   (3xTF32, mma.sync)
// ---------------------------------------------------------------------------
template <bool RELU>
__global__ __launch_bounds__(256, 2)
void k_gemm(const float* __restrict__ A, const float* __restrict__ W,
            const float* __restrict__ bias, float* __restrict__ C,
            int N, int KA, int KW)
{
    extern __shared__ char smem[];
    const uint32_t sb = smem_u32(smem);

    const int tid  = threadIdx.x;
    const int bm   = blockIdx.y * 128;
    const int n0   = blockIdx.x * 128;
    const int lane = tid & 31;
    const int wid  = tid >> 5;
    const int wm   = wid & 3;          // 0..3 -> 32 rows each
    const int wn   = wid >> 2;         // 0..1 -> 64 cols each
    const int grp  = lane >> 2;
    const int tig  = lane & 3;

    // ---- cp.async load mappings (BK=32) ----
    // A: 128 rows x 32k; thread -> row tid>>1, k base (tid&1)*16, 4 chunks
    //    (store bank-groups verified: 4 phases per 512B round = optimal)
    const int a_row = tid >> 1;
    const int a_k0  = (tid & 1) * 16;
    // B: two 16-row halves; per half: krow tid>>4, n chunks (tid&15), +16
    //    (identical to R7's conflict-free linear mapping)
    const int b_kr  = tid >> 4;
    const int b_nf  = (tid & 15) * 4;

    const long a_rowbase = (long)(bm + a_row) * KA;
    const int  n_ok0 = (n0 + b_nf)      < N ? 16 : 0;
    const int  n_ok1 = (n0 + b_nf + 64) < N ? 16 : 0;

    const int T = (KA + BK - 1) >> 5;

    auto load_stage = [&](int t, int slot) {
        uint32_t st = sb + slot * STAGE_BYTES;
        // A
        {
            uint32_t d = st + (a_row * A_STRIDE + a_k0) * 4;
#pragma unroll
            for (int u = 0; u < 4; u++) {
                int kg = t * BK + a_k0 + 4 * u;
                int sz = (kg < KA) ? 16 : 0;
                int kc = (kg < KA) ? kg : 0;
                cp16(d + u * 16, A + a_rowbase + kc, sz);
            }
        }
        // B: two 16-k halves, R7 mapping each
#pragma unroll
        for (int h = 0; h < 2; h++) {
            int kr  = t * BK + h * 16 + b_kr;
            int kok = kr < KW;
            long rb = (long)(kok ? kr : 0) * N + n0;
            uint32_t d = st + A_BYTES + ((h * 16 + b_kr) * B_STRIDE + b_nf) * 4;
            cp16(d,       W + rb + b_nf,      kok ? n_ok0 : 0);
            cp16(d + 256, W + rb + b_nf + 64, kok ? n_ok1 : 0);
        }
    };

    float c[2][8][4];
#pragma unroll
    for (int mt = 0; mt < 2; mt++)
#pragma unroll
        for (int nt = 0; nt < 8; nt++)
#pragma unroll
            for (int j = 0; j < 4; j++) c[mt][nt][j] = 0.0f;

    // prologue: stages 0,1
    if (0 < T) load_stage(0, 0);
    CP_COMMIT();
    if (1 < T) load_stage(1, 1);
    CP_COMMIT();

    int cslot = 0, lslot = 2;
    for (int t = 0; t < T; t++) {
        CP_WAIT1();
        __syncthreads();
        if (t + 2 < T) load_stage(t + 2, lslot);
        CP_COMMIT();

        const float* As = (const float*)(smem + cslot * STAGE_BYTES);
        const float* Bs = (const float*)(smem + cslot * STAGE_BYTES + A_BYTES);

#pragma unroll
        for (int kk = 0; kk < BK; kk += 8) {
            float ah[2][4], al[2][4];
#pragma unroll
            for (int mt = 0; mt < 2; mt++) {
                int rb = (wm * 32 + mt * 16 + grp) * A_STRIDE + kk + tig;
                split(As[rb],                    ah[mt][0], al[mt][0]);
                split(As[rb + 8 * A_STRIDE],     ah[mt][1], al[mt][1]);
                split(As[rb + 4],                ah[mt][2], al[mt][2]);
                split(As[rb + 8 * A_STRIDE + 4], ah[mt][3], al[mt][3]);
            }
#pragma unroll
            for (int nt = 0; nt < 8; nt++) {
                int cb = wn * 64 + nt * 8 + grp;
                float bh[2], bl[2];
                split(Bs[(kk + tig) * B_STRIDE + cb],     bh[0], bl[0]);
                split(Bs[(kk + tig + 4) * B_STRIDE + cb], bh[1], bl[1]);
#pragma unroll
                for (int mt = 0; mt < 2; mt++) {
                    mma8(c[mt][nt], ah[mt], bh);   // hi*hi
                    mma8(c[mt][nt], al[mt], bh);   // lo*hi
                    mma8(c[mt][nt], ah[mt], bl);   // hi*lo
                }
            }
        }
        cslot = (cslot == NSTAGE - 1) ? 0 : cslot + 1;
        lslot = (lslot == NSTAGE - 1) ? 0 : lslot + 1;
    }

    // epilogue: bias (+ relu), guarded stores
#pragma unroll
    for (int mt = 0; mt < 2; mt++) {
        int r = bm + wm * 32 + mt * 16 + grp;
#pragma unroll
        for (int nt = 0; nt < 8; nt++) {
            int col = n0 + wn * 64 + nt * 8 + tig * 2;
            if (col < N) {
                float bv0 = bias[col], bv1 = bias[col + 1];
                float v0 = c[mt][nt][0] + bv0;
                float v1 = c[mt][nt][1] + bv1;
                float v2 = c[mt][nt][2] + bv0;
                float v3 = c[mt][nt][3] + bv1;
                if (RELU) {
                    v0 = fmaxf(v0, 0.f); v1 = fmaxf(v1, 0.f);
                    v2 = fmaxf(v2, 0.f); v3 = fmaxf(v3, 0.f);
                }
                C[(long)r * N + col]           = v0;
                C[(long)r * N + col + 1]       = v1;
                C[(long)(r + 8) * N + col]     = v2;
                C[(long)(r + 8) * N + col + 1] = v3;
            }
        }
    }
}

// ---------------------------------------------------------------------------
// _H epilogue (exact replication of reference index gymnastics).
// ---------------------------------------------------------------------------
__global__ void k_h(const float* __restrict__ q, const float* __restrict__ w,
                    float* __restrict__ hq) {
    const int i  = blockIdx.x;   // 0..31
    const int l2 = threadIdx.x;  // 0..255
    __shared__ int   s_ind[LL];
    __shared__ float s_sel[LL * 4];

    const int rsel = l2 >> 6;
    const int lb   = (l2 & 63) * 4;

    const float w0 = w[(i * LL + l2) * RR + 0];
    const float w1 = w[(i * LL + l2) * RR + 1];
    const float w2 = w[(i * LL + l2) * RR + 2];
    const float w3 = w[(i * LL + l2) * RR + 3];

    float best = -3.402823466e38f;
    int bk = 0;
    const int nb = (64 * i) & 511;
    for (int k = 0; k < 64; ++k) {
        int n  = (nb + k) & 511;
        int bp = n >> 4, a = n & 15;
        int sbp = (bp >> 2) + ((bp & 3) << 3);
        const float* qp = q + ((long)(sbp * LL + lb) * AA + a) * RR + rsel;
        float u = qp[0] * w0 + qp[64] * w1 + qp[128] * w2 + qp[192] * w3;
        if (u > best) { best = u; bk = k; }
    }
    s_ind[l2] = bk;
    {
        int n  = (nb + bk) & 511;
        int bp = n >> 4, a = n & 15;
        int sbp = (bp >> 2) + ((bp & 3) << 3);
        const float* qp = q + ((long)(sbp * LL + lb) * AA + a) * RR + rsel;
        s_sel[l2 * 4 + 0] = qp[0];
        s_sel[l2 * 4 + 1] = qp[64];
        s_sel[l2 * 4 + 2] = qp[128];
        s_sel[l2 * 4 + 3] = qp[192];
    }
    __syncthreads();

    int key = bk, pos = 0;
    for (int j = 0; j < LL; ++j) {
        int kj = s_ind[j];
        pos += (kj < key) || (kj == key && j < l2);
    }
    float* o = hq + (long)(i * LL + pos) * 4;
    o[0] = s_sel[l2 * 4 + 0];
    o[1] = s_sel[l2 * 4 + 1];
    o[2] = s_sel[l2 * 4 + 2];
    o[3] = s_sel[l2 * 4 + 3];
}

// ---------------------------------------------------------------------------
// Launch
// ---------------------------------------------------------------------------
extern "C" void kernel_launch(void* const* d_in, const int* in_sizes, int n_in,
                              void* d_out, int out_size) {
    const float* state = (const float*)d_in[0];
    const float* pref  = (const float*)d_in[1];
    const float* W1 = (const float*)d_in[3];
    const float* b1 = (const float*)d_in[4];
    const float* W2 = (const float*)d_in[5];
    const float* b2 = (const float*)d_in[6];
    const float* W3 = (const float*)d_in[7];
    const float* b3 = (const float*)d_in[8];
    const float* W4 = (const float*)d_in[9];
    const float* b4 = (const float*)d_in[10];
    const float* W5 = (const float*)d_in[11];
    const float* b5 = (const float*)d_in[12];

    float* out = (float*)d_out;
    float* hq  = out;                        // [8192, 4]
    float* q   = out + BB * LL * RR;         // [32, 256, 16, 4]

    float *x0, *a1, *a2, *a3, *a4;
    cudaGetSymbolAddress((void**)&x0, g_x0);
    cudaGetSymbolAddress((void**)&a1, g_a1);
    cudaGetSymbolAddress((void**)&a2, g_a2);
    cudaGetSymbolAddress((void**)&a3, g_a3);
    cudaGetSymbolAddress((void**)&a4, g_a4);

    cudaFuncSetAttribute(k_gemm<true>,  cudaFuncAttributeMaxDynamicSharedMemorySize, SMB);
    cudaFuncSetAttribute(k_gemm<false>, cudaFuncAttributeMaxDynamicSharedMemorySize, SMB);

    k_concat<<<(M_TOK * K0P + 255) / 256, 256>>>(state, pref, x0);

    {
        dim3 g((D1 + 127) / 128, M_TOK / 128);
        k_gemm<true><<<g, 256, SMB>>>(x0, W1, b1, a1, D1, K0P, K0);
    }
    {
        dim3 g((D2 + 127) / 128, M_TOK / 128);
        k_gemm<true><<<g, 256, SMB>>>(a1, W2, b2, a2, D2, D1, D1);
    }
    {
        dim3 g((D3 + 127) / 128, M_TOK / 128);
        k_gemm<true><<<g, 256, SMB>>>(a2, W3, b3, a3, D3, D2, D2);
    }
    {
        dim3 g((D4 + 127) / 128, M_TOK / 128);
        k_gemm<true><<<g, 256, SMB>>>(a3, W4, b4, a4, D4, D3, D3);
    }
    {
        dim3 g(1, M_TOK / 128);
        k_gemm<false><<<g, 256, SMB>>>(a4, W5, b5, q, D5, D4, D4);
    }

    k_h<<<BB, LL>>>(q, pref, hq);
}

// round 11
// speedup vs baseline: 1.8728x; 1.2345x over previous
#include <cuda_runtime.h>
#include <cstdint>

// ---------------------------------------------------------------------------
// Problem constants
// ---------------------------------------------------------------------------
#define BB 32
#define LL 256
#define SS 128
#define AA 16
#define RR 4
#define M_TOK 8192        // B*L
#define K0 132            // S + R
#define K0P 136           // padded to /8
#define D1 2112
#define D2 4224
#define D3 8448
#define D4 4224
#define D5 64

// GEMM geometry: CTA 128x128, BK=16, 8 warps (4x2) of 32x64, raw-f32 smem.
// hi*hi in tf32-k8; cross corrections in fp16-k16 (fp16 holds tf32-hi exactly).
#define BK 16
#define A_STRIDE 20                      // floats per A row (16 + 4 pad)
#define B_STRIDE 136                     // floats per B k-row (128 + 8 pad)
#define A_BYTES (128 * A_STRIDE * 4)     // 10240
#define B_BYTES (BK * B_STRIDE * 4)      // 8704
#define STAGE_BYTES (A_BYTES + B_BYTES)  // 18944
#define NSTAGE 4
#define SMB (NSTAGE * STAGE_BYTES)       // 75776

// ---------------------------------------------------------------------------
// Scratch (static device globals; no allocation at runtime)
// ---------------------------------------------------------------------------
__device__ float g_x0[M_TOK * K0P];
__device__ float g_a1[M_TOK * D1];
__device__ float g_a2[M_TOK * D2];
__device__ float g_a3[M_TOK * D3];
__device__ float g_a4[M_TOK * D4];

// ---------------------------------------------------------------------------
// Helpers
// ---------------------------------------------------------------------------
__device__ __forceinline__ uint32_t smem_u32(const void* p) {
    uint32_t a;
    asm("{ .reg .u64 t; cvta.to.shared.u64 t, %1; cvt.u32.u64 %0, t; }" : "=r"(a) : "l"(p));
    return a;
}

__device__ __forceinline__ void cp16(uint32_t dst, const void* src, int pred16) {
    asm volatile("cp.async.cg.shared.global [%0], [%1], 16, %2;"
                 :: "r"(dst), "l"(src), "r"(pred16) : "memory");
}
#define CP_COMMIT() asm volatile("cp.async.commit_group;" ::: "memory")
#define CP_WAIT2()  asm volatile("cp.async.wait_group 2;" ::: "memory")

// exact tf32-hi by mask-truncation (11-bit mantissa -> fp16-exact)
__device__ __forceinline__ float hi_of(float x) {
    return __uint_as_float(__float_as_uint(x) & 0xFFFFE000u);
}

// pack two f32 into f16x2: result.lo = x0 (lower k), result.hi = x1
__device__ __forceinline__ uint32_t pk16(float x1, float x0) {
    uint32_t r;
    asm("cvt.rn.f16x2.f32 %0, %1, %2;" : "=r"(r) : "f"(x1), "f"(x0));
    return r;
}

__device__ __forceinline__ void mma8(float* c, const float* a, const float* b) {
    asm volatile(
        "mma.sync.aligned.m16n8k8.row.col.f32.tf32.tf32.f32 "
        "{%0,%1,%2,%3},{%4,%5,%6,%7},{%8,%9},{%0,%1,%2,%3};\n"
        : "+f"(c[0]), "+f"(c[1]), "+f"(c[2]), "+f"(c[3])
        : "r"(__float_as_uint(a[0])), "r"(__float_as_uint(a[1])),
          "r"(__float_as_uint(a[2])), "r"(__float_as_uint(a[3])),
          "r"(__float_as_uint(b[0])), "r"(__float_as_uint(b[1])));
}

__device__ __forceinline__ void mma16f(float* c, const uint32_t* a, const uint32_t* b) {
    asm volatile(
        "mma.sync.aligned.m16n8k16.row.col.f32.f16.f16.f32 "
        "{%0,%1,%2,%3},{%4,%5,%6,%7},{%8,%9},{%0,%1,%2,%3};\n"
        : "+f"(c[0]), "+f"(c[1]), "+f"(c[2]), "+f"(c[3])
        : "r"(a[0]), "r"(a[1]), "r"(a[2]), "r"(a[3]), "r"(b[0]), "r"(b[1]));
}

// ---------------------------------------------------------------------------
// Concat: X0[row, 0:128] = state, [128:132] = preference, [132:136] = 0
// ---------------------------------------------------------------------------
__global__ void k_concat(const float* __restrict__ st, const float* __restrict__ pf,
                         float* __restrict__ x0) {
    int idx = blockIdx.x * blockDim.x + threadIdx.x;
    if (idx >= M_TOK * K0P) return;
    int row = idx / K0P;
    int c   = idx - row * K0P;
    float v;
    if (c < SS)        v = st[row * SS + c];
    else if (c < K0)   v = pf[row * RR + (c - SS)];
    else               v = 0.0f;
    x0[idx] = v;
}

// ---------------------------------------------------------------------------
// GEMM: C[M,N] = act(A[M,KA] @ W[KW,N] + bias)
// tf32 hi*hi  +  fp16-k16 (lo*hi + hi*lo) corrections
// ---------------------------------------------------------------------------
template <bool RELU>
__global__ __launch_bounds__(256, 2)
void k_gemm(const float* __restrict__ A, const float* __restrict__ W,
            const float* __restrict__ bias, float* __restrict__ C,
            int N, int KA, int KW)
{
    extern __shared__ char smem[];
    const uint32_t sb = smem_u32(smem);

    const int tid  = threadIdx.x;
    const int bm   = blockIdx.y * 128;
    const int n0   = blockIdx.x * 128;
    const int lane = tid & 31;
    const int wid  = tid >> 5;
    const int wm   = wid & 3;          // 0..3 -> 32 rows each
    const int wn   = wid >> 2;         // 0..1 -> 64 cols each
    const int grp  = lane >> 2;
    const int tig  = lane & 3;

    // ---- cp.async load mappings (identical to R7) ----
    const int a_row = tid >> 1;
    const int a_c0  = (tid & 1) * 2;
    const int b_kr  = tid >> 4;
    const int b_nf  = (tid & 15) * 4;

    const long a_rowbase = (long)(bm + a_row) * KA;
    const int  n_ok0 = (n0 + b_nf)      < N ? 16 : 0;
    const int  n_ok1 = (n0 + b_nf + 64) < N ? 16 : 0;

    const int T = (KA + BK - 1) >> 4;

    auto load_stage = [&](int t, int slot) {
        uint32_t st = sb + slot * STAGE_BYTES;
        // A (raw f32)
        {
            int kg0 = t * BK + a_c0 * 4;
            uint32_t d = st + (a_row * A_STRIDE + a_c0 * 4) * 4;
#pragma unroll
            for (int u = 0; u < 2; u++) {
                int kg = kg0 + u * 4;
                int sz = (kg < KA) ? 16 : 0;
                int kc = (kg < KA) ? kg : 0;
                cp16(d + u * 16, A + a_rowbase + kc, sz);
            }
        }
        // B (raw f32)
        {
            int kr  = t * BK + b_kr;
            int kok = kr < KW;
            long rb = (long)(kok ? kr : 0) * N + n0;
            uint32_t d = st + A_BYTES + (b_kr * B_STRIDE + b_nf) * 4;
            cp16(d,       W + rb + b_nf,      kok ? n_ok0 : 0);
            cp16(d + 256, W + rb + b_nf + 64, kok ? n_ok1 : 0);
        }
    };

    float c[2][8][4];
#pragma unroll
    for (int mt = 0; mt < 2; mt++)
#pragma unroll
        for (int nt = 0; nt < 8; nt++)
#pragma unroll
            for (int j = 0; j < 4; j++) c[mt][nt][j] = 0.0f;

    // prologue: stages 0..2
#pragma unroll
    for (int s = 0; s < NSTAGE - 1; s++) {
        if (s < T) load_stage(s, s);
        CP_COMMIT();
    }

    for (int t = 0; t < T; t++) {
        CP_WAIT2();
        __syncthreads();
        {
            int lt = t + NSTAGE - 1;
            if (lt < T) load_stage(lt, lt & (NSTAGE - 1));
            CP_COMMIT();
        }
        const int slot = t & (NSTAGE - 1);
        const float* As = (const float*)(smem + slot * STAGE_BYTES);
        const float* Bs = (const float*)(smem + slot * STAGE_BYTES + A_BYTES);

        // ---- A fp16 fragments (k16-wide), shared across the nt loop ----
        // m16n8k16 A frag: reg = {r0:(grp,k 2tig..+1), r1:(grp+8,same),
        //                         r2:(grp,k 2tig+8..+9), r3:(grp+8,same)}
        uint32_t aH[2][4], aL[2][4];
#pragma unroll
        for (int mt = 0; mt < 2; mt++) {
            int R = wm * 32 + mt * 16 + grp;
#pragma unroll
            for (int kp = 0; kp < 2; kp++) {
#pragma unroll
                for (int rr = 0; rr < 2; rr++) {
                    float2 v = *(const float2*)&As[(R + 8 * rr) * A_STRIDE + kp * 8 + 2 * tig];
                    float h0 = hi_of(v.x), h1 = hi_of(v.y);
                    aH[mt][kp * 2 + rr] = pk16(h1, h0);
                    aL[mt][kp * 2 + rr] = pk16(v.y - h1, v.x - h0);
                }
            }
        }

        // ---- tf32 hi*hi ----
#pragma unroll
        for (int kk = 0; kk < BK; kk += 8) {
            float ah[2][4];
#pragma unroll
            for (int mt = 0; mt < 2; mt++) {
                int rb = (wm * 32 + mt * 16 + grp) * A_STRIDE + kk + tig;
                ah[mt][0] = hi_of(As[rb]);
                ah[mt][1] = hi_of(As[rb + 8 * A_STRIDE]);
                ah[mt][2] = hi_of(As[rb + 4]);
                ah[mt][3] = hi_of(As[rb + 8 * A_STRIDE + 4]);
            }
#pragma unroll
            for (int nt = 0; nt < 8; nt++) {
                int cb = wn * 64 + nt * 8 + grp;
                float bh[2];
                bh[0] = hi_of(Bs[(kk + tig) * B_STRIDE + cb]);
                bh[1] = hi_of(Bs[(kk + tig + 4) * B_STRIDE + cb]);
                mma8(c[0][nt], ah[0], bh);
                mma8(c[1][nt], ah[1], bh);
            }
        }

        // ---- fp16 cross corrections (lo*hi + hi*lo), k16 per MMA ----
        // m16n8k16 B frag: b0 = (k 2tig..+1, n grp), b1 = (k 2tig+8..+9, n grp)
#pragma unroll
        for (int nt = 0; nt < 8; nt++) {
            int cb = wn * 64 + nt * 8 + grp;
            uint32_t bH[2], bL[2];
#pragma unroll
            for (int kp = 0; kp < 2; kp++) {
                float x0 = Bs[(kp * 8 + 2 * tig) * B_STRIDE + cb];
                float x1 = Bs[(kp * 8 + 2 * tig + 1) * B_STRIDE + cb];
                float h0 = hi_of(x0), h1 = hi_of(x1);
                bH[kp] = pk16(h1, h0);
                bL[kp] = pk16(x1 - h1, x0 - h0);
            }
            mma16f(c[0][nt], aL[0], bH);
            mma16f(c[0][nt], aH[0], bL);
            mma16f(c[1][nt], aL[1], bH);
            mma16f(c[1][nt], aH[1], bL);
        }
    }

    // epilogue: bias (+ relu), guarded stores
#pragma unroll
    for (int mt = 0; mt < 2; mt++) {
        int r = bm + wm * 32 + mt * 16 + grp;
#pragma unroll
        for (int nt = 0; nt < 8; nt++) {
            int col = n0 + wn * 64 + nt * 8 + tig * 2;
            if (col < N) {
                float bv0 = bias[col], bv1 = bias[col + 1];
                float v0 = c[mt][nt][0] + bv0;
                float v1 = c[mt][nt][1] + bv1;
                float v2 = c[mt][nt][2] + bv0;
                float v3 = c[mt][nt][3] + bv1;
                if (RELU) {
                    v0 = fmaxf(v0, 0.f); v1 = fmaxf(v1, 0.f);
                    v2 = fmaxf(v2, 0.f); v3 = fmaxf(v3, 0.f);
                }
                C[(long)r * N + col]           = v0;
                C[(long)r * N + col + 1]       = v1;
                C[(long)(r + 8) * N + col]     = v2;
                C[(long)(r + 8) * N + col + 1] = v3;
            }
        }
    }
}

// ---------------------------------------------------------------------------
// _H epilogue (exact replication of reference index gymnastics).
// ---------------------------------------------------------------------------
__global__ void k_h(const float* __restrict__ q, const float* __restrict__ w,
                    float* __restrict__ hq) {
    const int i  = blockIdx.x;   // 0..31
    const int l2 = threadIdx.x;  // 0..255
    __shared__ int   s_ind[LL];
    __shared__ float s_sel[LL * 4];

    const int rsel = l2 >> 6;
    const int lb   = (l2 & 63) * 4;

    const float w0 = w[(i * LL + l2) * RR + 0];
    const float w1 = w[(i * LL + l2) * RR + 1];
    const float w2 = w[(i * LL + l2) * RR + 2];
    const float w3 = w[(i * LL + l2) * RR + 3];

    float best = -3.402823466e38f;
    int bk = 0;
    const int nb = (64 * i) & 511;
    for (int k = 0; k < 64; ++k) {
        int n  = (nb + k) & 511;
        int bp = n >> 4, a = n & 15;
        int sbp = (bp >> 2) + ((bp & 3) << 3);
        const float* qp = q + ((long)(sbp * LL + lb) * AA + a) * RR + rsel;
        float u = qp[0] * w0 + qp[64] * w1 + qp[128] * w2 + qp[192] * w3;
        if (u > best) { best = u; bk = k; }
    }
    s_ind[l2] = bk;
    {
        int n  = (nb + bk) & 511;
        int bp = n >> 4, a = n & 15;
        int sbp = (bp >> 2) + ((bp & 3) << 3);
        const float* qp = q + ((long)(sbp * LL + lb) * AA + a) * RR + rsel;
        s_sel[l2 * 4 + 0] = qp[0];
        s_sel[l2 * 4 + 1] = qp[64];
        s_sel[l2 * 4 + 2] = qp[128];
        s_sel[l2 * 4 + 3] = qp[192];
    }
    __syncthreads();

    int key = bk, pos = 0;
    for (int j = 0; j < LL; ++j) {
        int kj = s_ind[j];
        pos += (kj < key) || (kj == key && j < l2);
    }
    float* o = hq + (long)(i * LL + pos) * 4;
    o[0] = s_sel[l2 * 4 + 0];
    o[1] = s_sel[l2 * 4 + 1];
    o[2] = s_sel[l2 * 4 + 2];
    o[3] = s_sel[l2 * 4 + 3];
}

// ---------------------------------------------------------------------------
// Launch
// ---------------------------------------------------------------------------
extern "C" void kernel_launch(void* const* d_in, const int* in_sizes, int n_in,
                              void* d_out, int out_size) {
    const float* state = (const float*)d_in[0];
    const float* pref  = (const float*)d_in[1];
    const float* W1 = (const float*)d_in[3];
    const float* b1 = (const float*)d_in[4];
    const float* W2 = (const float*)d_in[5];
    const float* b2 = (const float*)d_in[6];
    const float* W3 = (const float*)d_in[7];
    const float* b3 = (const float*)d_in[8];
    const float* W4 = (const float*)d_in[9];
    const float* b4 = (const float*)d_in[10];
    const float* W5 = (const float*)d_in[11];
    const float* b5 = (const float*)d_in[12];

    float* out = (float*)d_out;
    float* hq  = out;                        // [8192, 4]
    float* q   = out + BB * LL * RR;         // [32, 256, 16, 4]

    float *x0, *a1, *a2, *a3, *a4;
    cudaGetSymbolAddress((void**)&x0, g_x0);
    cudaGetSymbolAddress((void**)&a1, g_a1);
    cudaGetSymbolAddress((void**)&a2, g_a2);
    cudaGetSymbolAddress((void**)&a3, g_a3);
    cudaGetSymbolAddress((void**)&a4, g_a4);

    cudaFuncSetAttribute(k_gemm<true>,  cudaFuncAttributeMaxDynamicSharedMemorySize, SMB);
    cudaFuncSetAttribute(k_gemm<false>, cudaFuncAttributeMaxDynamicSharedMemorySize, SMB);

    k_concat<<<(M_TOK * K0P + 255) / 256, 256>>>(state, pref, x0);

    {
        dim3 g((D1 + 127) / 128, M_TOK / 128);
        k_gemm<true><<<g, 256, SMB>>>(x0, W1, b1, a1, D1, K0P, K0);
    }
    {
        dim3 g((D2 + 127) / 128, M_TOK / 128);
        k_gemm<true><<<g, 256, SMB>>>(a1, W2, b2, a2, D2, D1, D1);
    }
    {
        dim3 g((D3 + 127) / 128, M_TOK / 128);
        k_gemm<true><<<g, 256, SMB>>>(a2, W3, b3, a3, D3, D2, D2);
    }
    {
        dim3 g((D4 + 127) / 128, M_TOK / 128);
        k_gemm<true><<<g, 256, SMB>>>(a3, W4, b4, a4, D4, D3, D3);
    }
    {
        dim3 g(1, M_TOK / 128);
        k_gemm<false><<<g, 256, SMB>>>(a4, W5, b5, q, D5, D4, D4);
    }

    k_h<<<BB, LL>>>(q, pref, hq);
}

// round 12
// speedup vs baseline: 2.2577x; 1.2055x over previous
#include <cuda_runtime.h>
#include <cstdint>

// ---------------------------------------------------------------------------
// Problem constants
// ---------------------------------------------------------------------------
#define BB 32
#define LL 256
#define SS 128
#define AA 16
#define RR 4
#define M_TOK 8192        // B*L
#define K0 132            // S + R
#define K0P 136           // padded to /8
#define D1 2112
#define D2 4224
#define D3 8448
#define D4 4224
#define D5 64

// GEMM geometry: CTA 128x128, BK=16, 8 warps (4x2) of 32x64, raw-f32 smem.
// Full 3-term fp16 scheme: x = hi + lo (hi = tf32-style 11-bit truncate,
// exactly representable in fp16). D += hi*hi + lo*hi + hi*lo, all m16n8k16.f16
// with fp32 accumulate. Dropped lo*lo ~ 2^-22 relative.
#define BK 16
#define A_STRIDE 20                      // floats per A row (16 + 4 pad)
#define B_STRIDE 136                     // floats per B k-row (128 + 8 pad)
#define A_BYTES (128 * A_STRIDE * 4)     // 10240
#define B_BYTES (BK * B_STRIDE * 4)      // 8704
#define STAGE_BYTES (A_BYTES + B_BYTES)  // 18944
#define NSTAGE 4
#define SMB (NSTAGE * STAGE_BYTES)       // 75776

// ---------------------------------------------------------------------------
// Scratch (static device globals; no allocation at runtime)
// ---------------------------------------------------------------------------
__device__ float g_x0[M_TOK * K0P];
__device__ float g_a1[M_TOK * D1];
__device__ float g_a2[M_TOK * D2];
__device__ float g_a3[M_TOK * D3];
__device__ float g_a4[M_TOK * D4];

// ---------------------------------------------------------------------------
// Helpers
// ---------------------------------------------------------------------------
__device__ __forceinline__ uint32_t smem_u32(const void* p) {
    uint32_t a;
    asm("{ .reg .u64 t; cvta.to.shared.u64 t, %1; cvt.u32.u64 %0, t; }" : "=r"(a) : "l"(p));
    return a;
}

__device__ __forceinline__ void cp16(uint32_t dst, const void* src, int pred16) {
    asm volatile("cp.async.cg.shared.global [%0], [%1], 16, %2;"
                 :: "r"(dst), "l"(src), "r"(pred16) : "memory");
}
#define CP_COMMIT() asm volatile("cp.async.commit_group;" ::: "memory")
#define CP_WAIT2()  asm volatile("cp.async.wait_group 2;" ::: "memory")

// exact 11-bit-mantissa hi by mask-truncation (fp16-exact, tf32-equivalent)
__device__ __forceinline__ float hi_of(float x) {
    return __uint_as_float(__float_as_uint(x) & 0xFFFFE000u);
}

// pack two f32 into f16x2: result.lo = x0 (lower k), result.hi = x1
__device__ __forceinline__ uint32_t pk16(float x1, float x0) {
    uint32_t r;
    asm("cvt.rn.f16x2.f32 %0, %1, %2;" : "=r"(r) : "f"(x1), "f"(x0));
    return r;
}

__device__ __forceinline__ void mma16f(float* c, const uint32_t* a, const uint32_t* b) {
    asm volatile(
        "mma.sync.aligned.m16n8k16.row.col.f32.f16.f16.f32 "
        "{%0,%1,%2,%3},{%4,%5,%6,%7},{%8,%9},{%0,%1,%2,%3};\n"
        : "+f"(c[0]), "+f"(c[1]), "+f"(c[2]), "+f"(c[3])
        : "r"(a[0]), "r"(a[1]), "r"(a[2]), "r"(a[3]), "r"(b[0]), "r"(b[1]));
}

// ---------------------------------------------------------------------------
// Concat: X0[row, 0:128] = state, [128:132] = preference, [132:136] = 0
// ---------------------------------------------------------------------------
__global__ void k_concat(const float* __restrict__ st, const float* __restrict__ pf,
                         float* __restrict__ x0) {
    int idx = blockIdx.x * blockDim.x + threadIdx.x;
    if (idx >= M_TOK * K0P) return;
    int row = idx / K0P;
    int c   = idx - row * K0P;
    float v;
    if (c < SS)        v = st[row * SS + c];
    else if (c < K0)   v = pf[row * RR + (c - SS)];
    else               v = 0.0f;
    x0[idx] = v;
}

// ---------------------------------------------------------------------------
// GEMM: C[M,N] = act(A[M,KA] @ W[KW,N] + bias)
// 3-term fp16 (hi*hi + lo*hi + hi*lo), m16n8k16, fp32 accumulate
// ---------------------------------------------------------------------------
template <bool RELU>
__global__ __launch_bounds__(256, 2)
void k_gemm(const float* __restrict__ A, const float* __restrict__ W,
            const float* __restrict__ bias, float* __restrict__ C,
            int N, int KA, int KW)
{
    extern __shared__ char smem[];
    const uint32_t sb = smem_u32(smem);

    const int tid  = threadIdx.x;
    const int bm   = blockIdx.y * 128;
    const int n0   = blockIdx.x * 128;
    const int lane = tid & 31;
    const int wid  = tid >> 5;
    const int wm   = wid & 3;          // 0..3 -> 32 rows each
    const int wn   = wid >> 2;         // 0..1 -> 64 cols each
    const int grp  = lane >> 2;
    const int tig  = lane & 3;

    // ---- cp.async load mappings (identical to R7/R11) ----
    const int a_row = tid >> 1;
    const int a_c0  = (tid & 1) * 2;
    const int b_kr  = tid >> 4;
    const int b_nf  = (tid & 15) * 4;

    const long a_rowbase = (long)(bm + a_row) * KA;
    const int  n_ok0 = (n0 + b_nf)      < N ? 16 : 0;
    const int  n_ok1 = (n0 + b_nf + 64) < N ? 16 : 0;

    const int T = (KA + BK - 1) >> 4;

    auto load_stage = [&](int t, int slot) {
        uint32_t st = sb + slot * STAGE_BYTES;
        // A (raw f32)
        {
            int kg0 = t * BK + a_c0 * 4;
            uint32_t d = st + (a_row * A_STRIDE + a_c0 * 4) * 4;
#pragma unroll
            for (int u = 0; u < 2; u++) {
                int kg = kg0 + u * 4;
                int sz = (kg < KA) ? 16 : 0;
                int kc = (kg < KA) ? kg : 0;
                cp16(d + u * 16, A + a_rowbase + kc, sz);
            }
        }
        // B (raw f32)
        {
            int kr  = t * BK + b_kr;
            int kok = kr < KW;
            long rb = (long)(kok ? kr : 0) * N + n0;
            uint32_t d = st + A_BYTES + (b_kr * B_STRIDE + b_nf) * 4;
            cp16(d,       W + rb + b_nf,      kok ? n_ok0 : 0);
            cp16(d + 256, W + rb + b_nf + 64, kok ? n_ok1 : 0);
        }
    };

    float c[2][8][4];
#pragma unroll
    for (int mt = 0; mt < 2; mt++)
#pragma unroll
        for (int nt = 0; nt < 8; nt++)
#pragma unroll
            for (int j = 0; j < 4; j++) c[mt][nt][j] = 0.0f;

    // prologue: stages 0..2
#pragma unroll
    for (int s = 0; s < NSTAGE - 1; s++) {
        if (s < T) load_stage(s, s);
        CP_COMMIT();
    }

    for (int t = 0; t < T; t++) {
        CP_WAIT2();
        __syncthreads();
        {
            int lt = t + NSTAGE - 1;
            if (lt < T) load_stage(lt, lt & (NSTAGE - 1));
            CP_COMMIT();
        }
        const int slot = t & (NSTAGE - 1);
        const float* As = (const float*)(smem + slot * STAGE_BYTES);
        const float* Bs = (const float*)(smem + slot * STAGE_BYTES + A_BYTES);

        // ---- A fp16 fragments (k16-wide), shared across the nt loop ----
        // m16n8k16 A frag: reg = {r0:(grp,k 2tig..+1), r1:(grp+8,same),
        //                         r2:(grp,k 2tig+8..+9), r3:(grp+8,same)}
        uint32_t aH[2][4], aL[2][4];
#pragma unroll
        for (int mt = 0; mt < 2; mt++) {
            int R = wm * 32 + mt * 16 + grp;
#pragma unroll
            for (int kp = 0; kp < 2; kp++) {
#pragma unroll
                for (int rr = 0; rr < 2; rr++) {
                    float2 v = *(const float2*)&As[(R + 8 * rr) * A_STRIDE + kp * 8 + 2 * tig];
                    float h0 = hi_of(v.x), h1 = hi_of(v.y);
                    aH[mt][kp * 2 + rr] = pk16(h1, h0);
                    aL[mt][kp * 2 + rr] = pk16(v.y - h1, v.x - h0);
                }
            }
        }

        // ---- 3-term fp16 MMAs ----
        // m16n8k16 B frag: b0 = (k 2tig..+1, n grp), b1 = (k 2tig+8..+9, n grp)
#pragma unroll
        for (int nt = 0; nt < 8; nt++) {
            int cb = wn * 64 + nt * 8 + grp;
            uint32_t bH[2], bL[2];
#pragma unroll
            for (int kp = 0; kp < 2; kp++) {
                float x0 = Bs[(kp * 8 + 2 * tig) * B_STRIDE + cb];
                float x1 = Bs[(kp * 8 + 2 * tig + 1) * B_STRIDE + cb];
                float h0 = hi_of(x0), h1 = hi_of(x1);
                bH[kp] = pk16(h1, h0);
                bL[kp] = pk16(x1 - h1, x0 - h0);
            }
            mma16f(c[0][nt], aH[0], bH);   // hi*hi
            mma16f(c[0][nt], aL[0], bH);   // lo*hi
            mma16f(c[0][nt], aH[0], bL);   // hi*lo
            mma16f(c[1][nt], aH[1], bH);
            mma16f(c[1][nt], aL[1], bH);
            mma16f(c[1][nt], aH[1], bL);
        }
    }

    // epilogue: bias (+ relu), guarded stores
#pragma unroll
    for (int mt = 0; mt < 2; mt++) {
        int r = bm + wm * 32 + mt * 16 + grp;
#pragma unroll
        for (int nt = 0; nt < 8; nt++) {
            int col = n0 + wn * 64 + nt * 8 + tig * 2;
            if (col < N) {
                float bv0 = bias[col], bv1 = bias[col + 1];
                float v0 = c[mt][nt][0] + bv0;
                float v1 = c[mt][nt][1] + bv1;
                float v2 = c[mt][nt][2] + bv0;
                float v3 = c[mt][nt][3] + bv1;
                if (RELU) {
                    v0 = fmaxf(v0, 0.f); v1 = fmaxf(v1, 0.f);
                    v2 = fmaxf(v2, 0.f); v3 = fmaxf(v3, 0.f);
                }
                C[(long)r * N + col]           = v0;
                C[(long)r * N + col + 1]       = v1;
                C[(long)(r + 8) * N + col]     = v2;
                C[(long)(r + 8) * N + col + 1] = v3;
            }
        }
    }
}

// ---------------------------------------------------------------------------
// _H epilogue (exact replication of reference index gymnastics).
// ---------------------------------------------------------------------------
__global__ void k_h(const float* __restrict__ q, const float* __restrict__ w,
                    float* __restrict__ hq) {
    const int i  = blockIdx.x;   // 0..31
    const int l2 = threadIdx.x;  // 0..255
    __shared__ int   s_ind[LL];
    __shared__ float s_sel[LL * 4];

    const int rsel = l2 >> 6;
    const int lb   = (l2 & 63) * 4;

    const float w0 = w[(i * LL + l2) * RR + 0];
    const float w1 = w[(i * LL + l2) * RR + 1];
    const float w2 = w[(i * LL + l2) * RR + 2];
    const float w3 = w[(i * LL + l2) * RR + 3];

    float best = -3.402823466e38f;
    int bk = 0;
    const int nb = (64 * i) & 511;
    for (int k = 0; k < 64; ++k) {
        int n  = (nb + k) & 511;
        int bp = n >> 4, a = n & 15;
        int sbp = (bp >> 2) + ((bp & 3) << 3);
        const float* qp = q + ((long)(sbp * LL + lb) * AA + a) * RR + rsel;
        float u = qp[0] * w0 + qp[64] * w1 + qp[128] * w2 + qp[192] * w3;
        if (u > best) { best = u; bk = k; }
    }
    s_ind[l2] = bk;
    {
        int n  = (nb + bk) & 511;
        int bp = n >> 4, a = n & 15;
        int sbp = (bp >> 2) + ((bp & 3) << 3);
        const float* qp = q + ((long)(sbp * LL + lb) * AA + a) * RR + rsel;
        s_sel[l2 * 4 + 0] = qp[0];
        s_sel[l2 * 4 + 1] = qp[64];
        s_sel[l2 * 4 + 2] = qp[128];
        s_sel[l2 * 4 + 3] = qp[192];
    }
    __syncthreads();

    int key = bk, pos = 0;
    for (int j = 0; j < LL; ++j) {
        int kj = s_ind[j];
        pos += (kj < key) || (kj == key && j < l2);
    }
    float* o = hq + (long)(i * LL + pos) * 4;
    o[0] = s_sel[l2 * 4 + 0];
    o[1] = s_sel[l2 * 4 + 1];
    o[2] = s_sel[l2 * 4 + 2];
    o[3] = s_sel[l2 * 4 + 3];
}

// ---------------------------------------------------------------------------
// Launch
// ---------------------------------------------------------------------------
extern "C" void kernel_launch(void* const* d_in, const int* in_sizes, int n_in,
                              void* d_out, int out_size) {
    const float* state = (const float*)d_in[0];
    const float* pref  = (const float*)d_in[1];
    const float* W1 = (const float*)d_in[3];
    const float* b1 = (const float*)d_in[4];
    const float* W2 = (const float*)d_in[5];
    const float* b2 = (const float*)d_in[6];
    const float* W3 = (const float*)d_in[7];
    const float* b3 = (const float*)d_in[8];
    const float* W4 = (const float*)d_in[9];
    const float* b4 = (const float*)d_in[10];
    const float* W5 = (const float*)d_in[11];
    const float* b5 = (const float*)d_in[12];

    float* out = (float*)d_out;
    float* hq  = out;                        // [8192, 4]
    float* q   = out + BB * LL * RR;         // [32, 256, 16, 4]

    float *x0, *a1, *a2, *a3, *a4;
    cudaGetSymbolAddress((void**)&x0, g_x0);
    cudaGetSymbolAddress((void**)&a1, g_a1);
    cudaGetSymbolAddress((void**)&a2, g_a2);
    cudaGetSymbolAddress((void**)&a3, g_a3);
    cudaGetSymbolAddress((void**)&a4, g_a4);

    cudaFuncSetAttribute(k_gemm<true>,  cudaFuncAttributeMaxDynamicSharedMemorySize, SMB);
    cudaFuncSetAttribute(k_gemm<false>, cudaFuncAttributeMaxDynamicSharedMemorySize, SMB);

    k_concat<<<(M_TOK * K0P + 255) / 256, 256>>>(state, pref, x0);

    {
        dim3 g((D1 + 127) / 128, M_TOK / 128);
        k_gemm<true><<<g, 256, SMB>>>(x0, W1, b1, a1, D1, K0P, K0);
    }
    {
        dim3 g((D2 + 127) / 128, M_TOK / 128);
        k_gemm<true><<<g, 256, SMB>>>(a1, W2, b2, a2, D2, D1, D1);
    }
    {
        dim3 g((D3 + 127) / 128, M_TOK / 128);
        k_gemm<true><<<g, 256, SMB>>>(a2, W3, b3, a3, D3, D2, D2);
    }
    {
        dim3 g((D4 + 127) / 128, M_TOK / 128);
        k_gemm<true><<<g, 256, SMB>>>(a3, W4, b4, a4, D4, D3, D3);
    }
    {
        dim3 g(1, M_TOK / 128);
        k_gemm<false><<<g, 256, SMB>>>(a4, W5, b5, q, D5, D4, D4);
    }

    k_h<<<BB, LL>>>(q, pref, hq);
}